// round 9
// baseline (speedup 1.0000x reference)
#include <cuda_runtime.h>
#include <cstdint>

// Problem constants: B=64, R=32, N=16384, D=64, O=8
#define PB 64
#define PR 32
#define PN 16384
#define PD 64
#define PO 8

#define BLOCKS_PER_B 16
#define THREADS 256          // 8 warps
#define WARPS (THREADS / 32)
#define ROWS_PER_BLOCK (PN / BLOCKS_PER_B)   // 1024

// Global scratch (zero-initialized at load; the finalizing block resets it
// each run -> graph-replay-deterministic).
__device__ float        g_s[PB][PD];
__device__ float        g_cnt[PB];
__device__ unsigned int g_ticket[PB];

// acq_rel fetch-add on the ticket (replaces two __threadfence calls).
__device__ __forceinline__ unsigned int ticket_acq_rel(unsigned int* p) {
    unsigned int old;
    asm volatile("atom.acq_rel.gpu.global.add.u32 %0, [%1], 1;"
                 : "=r"(old) : "l"(p) : "memory");
    return old;
}

// ---------------------------------------------------------------------------
// Grid (BLOCKS_PER_B, PB), 256 threads.
// Phase 1a: each lane scans 4 rows (one int4 triplet, front-batched with the
//           l_local prefetch) and pushes valid row indices (~7.6/block) into
//           a shared compacted list.
// Phase 1b: 16 half-warps pull rows round-robin from the list — block-wide
//           load balancing kills the Poisson-max straggler warp. Each
//           half-warp: lane16 -> float4 slice of the 256B row, 4-step shfl
//           L2-normalize, accumulate, smem atomics into s[64].
// Phase 2:  last block per b (acq_rel ticket) finalizes 32 outputs from the
//           prefetched l_local rows and resets the scratch.
// ---------------------------------------------------------------------------
__global__ __launch_bounds__(THREADS)
void ssfw_fused_kernel(const float* __restrict__ l_local,
                       const float* __restrict__ h_context,
                       const float* __restrict__ lambda_so,
                       const int* __restrict__ center_o,
                       const int* __restrict__ o_types,
                       const int* __restrict__ adj_mask,
                       const int* __restrict__ two_hop_mask,
                       float* __restrict__ out) {
    __shared__ float s[PD];
    __shared__ int   list[ROWS_PER_BLOCK];
    __shared__ int   nlist;
    __shared__ int   sIsLast;

    const int b      = blockIdx.y;
    const int lane   = threadIdx.x & 31;
    const int warp   = threadIdx.x >> 5;
    const int half   = lane >> 4;        // 0 or 1
    const int lane16 = lane & 15;
    const unsigned hmask = 0xFFFFu << (16 * half);

    if (threadIdx.x < PD) s[threadIdx.x] = 0.0f;
    if (threadIdx.x == 0) nlist = 0;

    // ---- front-batched independent loads ----
    const int base = blockIdx.x * ROWS_PER_BLOCK + warp * (ROWS_PER_BLOCK / WARPS);
    const int vec  = (base >> 2) + lane;           // int4 index

    const int4* ot4 = (const int4*)(o_types      + (size_t)b * PN);
    const int4* am4 = (const int4*)(adj_mask     + (size_t)b * PN);
    const int4* th4 = (const int4*)(two_hop_mask + (size_t)b * PN);

    const int4 ot = __ldg(&ot4[vec]);
    const int4 am = __ldg(&am4[vec]);
    const int4 th = __ldg(&th4[vec]);

    // phase-2 prefetch: this warp's 4 l_local rows (r = warp + rr*8)
    float2 lv[PR / WARPS];
    #pragma unroll
    for (int rr = 0; rr < PR / WARPS; ++rr) {
        const int r = warp + rr * WARPS;
        lv[rr] = ((const float2*)(l_local + ((size_t)b * PR + r) * PD))[lane];
    }

    const int cb = center_o[b];

    const bool v0 = ((am.x | th.x) != 0) && (ot.x == cb);
    const bool v1 = ((am.y | th.y) != 0) && (ot.y == cb);
    const bool v2 = ((am.z | th.z) != 0) && (ot.z == cb);
    const bool v3 = ((am.w | th.w) != 0) && (ot.w == cb);

    __syncthreads();   // smem init (s, nlist) visible before pushes

    // ---- Phase 1a: push valid row indices into the shared list ----
    const int myrow0 = base + 4 * lane;
    if (v0) list[atomicAdd(&nlist, 1)] = myrow0 + 0;
    if (v1) list[atomicAdd(&nlist, 1)] = myrow0 + 1;
    if (v2) list[atomicAdd(&nlist, 1)] = myrow0 + 2;
    if (v3) list[atomicAdd(&nlist, 1)] = myrow0 + 3;

    __syncthreads();
    const int n = nlist;

    // ---- Phase 1b: balanced gather, 16 half-warps round-robin ----
    const float* ctxBase = h_context + (size_t)b * PN * PD;
    float ax = 0.0f, ay = 0.0f, az = 0.0f, aw = 0.0f;

    for (int idx = 2 * warp + half; idx < n; idx += 2 * WARPS) {
        const int row = list[idx];                 // smem broadcast
        const float4 v =
            ((const float4*)(ctxBase + (size_t)row * PD))[lane16];
        float ss = v.x * v.x + v.y * v.y + v.z * v.z + v.w * v.w;
        #pragma unroll
        for (int o = 8; o; o >>= 1)                // within the 16-lane half
            ss += __shfl_xor_sync(hmask, ss, o);
        const float inv = rsqrtf(fmaxf(ss, 1e-12f));
        ax += v.x * inv;
        ay += v.y * inv;
        az += v.z * inv;
        aw += v.w * inv;
    }

    // block-local reduction into smem
    if (ax != 0.0f || ay != 0.0f || az != 0.0f || aw != 0.0f) {
        atomicAdd(&s[4 * lane16 + 0], ax);
        atomicAdd(&s[4 * lane16 + 1], ay);
        atomicAdd(&s[4 * lane16 + 2], az);
        atomicAdd(&s[4 * lane16 + 3], aw);
    }
    __syncthreads();

    // warp 0 pushes the block partial; thread 0 bumps the acq_rel ticket.
    if (warp == 0) {
        atomicAdd(&g_s[b][2 * lane],     s[2 * lane]);
        atomicAdd(&g_s[b][2 * lane + 1], s[2 * lane + 1]);
        if (lane == 0) {
            atomicAdd(&g_cnt[b], (float)n);
            const unsigned old = ticket_acq_rel(&g_ticket[b]);
            sIsLast = (old == BLOCKS_PER_B - 1);
        }
    }
    __syncthreads();
    if (!sIsLast) return;

    // ---- Phase 2 (last block per b): finalize 32 outputs (lv prefetched) ----
    const float cntf  = g_cnt[b];
    const float invc9 = 1.0f / fmaxf(cntf, 1e-9f);
    const float invc1 = 1.0f / fmaxf(cntf, 1.0f);

    const float sx = g_s[b][2 * lane];
    const float sy = g_s[b][2 * lane + 1];

    #pragma unroll
    for (int rr = 0; rr < PR / WARPS; ++rr) {          // 4 rows per warp
        const int r = warp + rr * WARPS;
        const float2 v = lv[rr];
        float ss  = v.x * v.x + v.y * v.y;
        float dot = v.x * sx + v.y * sy;
        #pragma unroll
        for (int o = 16; o; o >>= 1) {
            ss  += __shfl_xor_sync(0xffffffffu, ss,  o);
            dot += __shfl_xor_sync(0xffffffffu, dot, o);
        }
        if (lane == 0) {
            const float inv = rsqrtf(fmaxf(ss, 1e-12f));
            const float avg = dot * inv * invc9;
            const float lam = lambda_so[r * PO + cb];
            out[b * PR + r] = fmaxf(lam * invc1, 0.0f) * (1.0f - avg);
        }
    }

    // ---- reset scratch for the next (graph-replayed) run ----
    __syncthreads();
    if (threadIdx.x < PD) g_s[b][threadIdx.x] = 0.0f;
    if (threadIdx.x == 0) { g_cnt[b] = 0.0f; g_ticket[b] = 0u; }
}

// ---------------------------------------------------------------------------
// Launch. Input order: l_local, h_context, lambda_so, center_o, o_types,
//                      adj_mask, two_hop_mask
// ---------------------------------------------------------------------------
extern "C" void kernel_launch(void* const* d_in, const int* in_sizes, int n_in,
                              void* d_out, int out_size) {
    const float* l_local   = (const float*)d_in[0];
    const float* h_context = (const float*)d_in[1];
    const float* lambda_so = (const float*)d_in[2];
    const int*   center_o  = (const int*)d_in[3];
    const int*   o_types   = (const int*)d_in[4];
    const int*   adj_mask  = (const int*)d_in[5];
    const int*   two_hop   = (const int*)d_in[6];
    float*       out       = (float*)d_out;

    dim3 grid(BLOCKS_PER_B, PB);
    ssfw_fused_kernel<<<grid, THREADS>>>(l_local, h_context, lambda_so,
                                         center_o, o_types, adj_mask, two_hop,
                                         out);
}

// round 10
// speedup vs baseline: 1.1720x; 1.1720x over previous
#include <cuda_runtime.h>
#include <cstdint>

// Problem constants: B=64, R=32, N=16384, D=64, O=8
#define PB 64
#define PR 32
#define PN 16384
#define PD 64
#define PO 8

#define BLOCKS_PER_B 16
#define THREADS 256          // 8 warps
#define WARPS (THREADS / 32)

// Global scratch (zero-initialized at load; the finalizing block resets it
// each run -> graph-replay-deterministic).
__device__ float        g_s[PB][PD];
__device__ float        g_cnt[PB];
__device__ unsigned int g_ticket[PB];

// acq_rel fetch-add on the ticket (replaces two __threadfence calls).
__device__ __forceinline__ unsigned int ticket_acq_rel(unsigned int* p) {
    unsigned int old;
    asm volatile("atom.acq_rel.gpu.global.add.u32 %0, [%1], 1;"
                 : "=r"(old) : "l"(p) : "memory");
    return old;
}

// fire-and-forget vector reduction: g_s push in 16 ops instead of 64
__device__ __forceinline__ void red_add_v4(float* p, float4 v) {
    asm volatile("red.global.add.v4.f32 [%0], {%1, %2, %3, %4};"
                 :: "l"(p), "f"(v.x), "f"(v.y), "f"(v.z), "f"(v.w)
                 : "memory");
}

// ---------------------------------------------------------------------------
// Grid (BLOCKS_PER_B, PB), 256 threads. Per warp: 128 rows = one int4 triplet
// per lane, front-batched with the warp's 4 l_local rows (phase-2 prefetch).
// Gather: two valid rows in flight per iteration via 16-lane half-warps
// (lane16 -> float4 slice of the 256B row, 4-step shfl reduce).
// Block partial pushed to g_s with red.v4; last block per b (acq_rel ticket)
// finalizes 32 outputs from prefetched l_local and resets scratch.
// ---------------------------------------------------------------------------
__global__ __launch_bounds__(THREADS)
void ssfw_fused_kernel(const float* __restrict__ l_local,
                       const float* __restrict__ h_context,
                       const float* __restrict__ lambda_so,
                       const int* __restrict__ center_o,
                       const int* __restrict__ o_types,
                       const int* __restrict__ adj_mask,
                       const int* __restrict__ two_hop_mask,
                       float* __restrict__ out) {
    __shared__ float s[PD];
    __shared__ float scnt;
    __shared__ int   sIsLast;

    const int b      = blockIdx.y;
    const int lane   = threadIdx.x & 31;
    const int warp   = threadIdx.x >> 5;
    const int half   = lane >> 4;        // 0 or 1
    const int lane16 = lane & 15;

    if (threadIdx.x < PD) s[threadIdx.x] = 0.0f;
    if (threadIdx.x == 0) scnt = 0.0f;

    // ---- front-batched independent loads ----
    const int rowsPerBlock = PN / BLOCKS_PER_B;            // 1024
    const int rowsPerWarp  = rowsPerBlock / WARPS;         // 128
    const int base         = blockIdx.x * rowsPerBlock + warp * rowsPerWarp;
    const int vec          = (base >> 2) + lane;           // int4 index

    const int4* ot4 = (const int4*)(o_types      + (size_t)b * PN);
    const int4* am4 = (const int4*)(adj_mask     + (size_t)b * PN);
    const int4* th4 = (const int4*)(two_hop_mask + (size_t)b * PN);

    const int4 ot = __ldg(&ot4[vec]);
    const int4 am = __ldg(&am4[vec]);
    const int4 th = __ldg(&th4[vec]);

    // phase-2 prefetch: this warp's 4 l_local rows (r = warp + rr*8)
    float2 lv[PR / WARPS];
    #pragma unroll
    for (int rr = 0; rr < PR / WARPS; ++rr) {
        const int r = warp + rr * WARPS;
        lv[rr] = ((const float2*)(l_local + ((size_t)b * PR + r) * PD))[lane];
    }

    const int cb = center_o[b];

    const bool v0 = ((am.x | th.x) != 0) && (ot.x == cb);
    const bool v1 = ((am.y | th.y) != 0) && (ot.y == cb);
    const bool v2 = ((am.z | th.z) != 0) && (ot.z == cb);
    const bool v3 = ((am.w | th.w) != 0) && (ot.w == cb);

    float ax = 0.0f, ay = 0.0f, az = 0.0f, aw = 0.0f;  // float4 slice acc
    int   cntw = 0;

    __syncthreads();   // smem zero-init visible

    const float* ctxBase = h_context + (size_t)b * PN * PD;

    // ---- gather: two valid rows in flight per iteration ----
    #pragma unroll
    for (int t = 0; t < 4; ++t) {
        const bool vt = (t == 0) ? v0 : (t == 1) ? v1 : (t == 2) ? v2 : v3;
        unsigned m = __ballot_sync(0xffffffffu, vt);
        cntw += __popc(m);
        while (m) {
            const int j0 = __ffs(m) - 1;
            m &= (m - 1);
            int j1 = -1;
            if (m) { j1 = __ffs(m) - 1; m &= (m - 1); }

            const int row0  = base + 4 * j0 + t;
            const int row1  = (j1 >= 0) ? (base + 4 * j1 + t) : row0;
            const int myrow = half ? row1 : row0;

            // 16 lanes x float4 = 256B row
            const float4 v =
                ((const float4*)(ctxBase + (size_t)myrow * PD))[lane16];
            float ss = v.x * v.x + v.y * v.y + v.z * v.z + v.w * v.w;
            #pragma unroll
            for (int o = 8; o; o >>= 1)      // stays within the 16-lane half
                ss += __shfl_xor_sync(0xffffffffu, ss, o);
            const float inv = rsqrtf(fmaxf(ss, 1e-12f));

            if (half == 0 || j1 >= 0) {      // half 1 idle when row1 absent
                ax += v.x * inv;
                ay += v.y * inv;
                az += v.z * inv;
                aw += v.w * inv;
            }
        }
    }

    // block-local reduction into smem (skip all-zero contributions)
    if (ax != 0.0f || ay != 0.0f || az != 0.0f || aw != 0.0f) {
        atomicAdd(&s[4 * lane16 + 0], ax);
        atomicAdd(&s[4 * lane16 + 1], ay);
        atomicAdd(&s[4 * lane16 + 2], az);
        atomicAdd(&s[4 * lane16 + 3], aw);
    }
    if (lane == 0 && cntw) atomicAdd(&scnt, (float)cntw);
    __syncthreads();

    // warp 0 pushes the block partial (16 red.v4); thread 0 bumps the ticket.
    if (warp == 0) {
        if (lane < 16) {
            const float4 sv = ((const float4*)s)[lane];
            red_add_v4(&g_s[b][4 * lane], sv);
        }
        if (lane == 0) {
            atomicAdd(&g_cnt[b], scnt);
            const unsigned old = ticket_acq_rel(&g_ticket[b]);
            sIsLast = (old == BLOCKS_PER_B - 1);
        }
    }
    __syncthreads();
    if (!sIsLast) return;

    // ---- Phase 2 (last block per b): finalize 32 outputs (lv prefetched) ----
    const float cntf  = g_cnt[b];
    const float invc9 = 1.0f / fmaxf(cntf, 1e-9f);
    const float invc1 = 1.0f / fmaxf(cntf, 1.0f);

    const float sx = g_s[b][2 * lane];
    const float sy = g_s[b][2 * lane + 1];

    #pragma unroll
    for (int rr = 0; rr < PR / WARPS; ++rr) {          // 4 rows per warp
        const int r = warp + rr * WARPS;
        const float2 v = lv[rr];
        float ss  = v.x * v.x + v.y * v.y;
        float dot = v.x * sx + v.y * sy;
        #pragma unroll
        for (int o = 16; o; o >>= 1) {
            ss  += __shfl_xor_sync(0xffffffffu, ss,  o);
            dot += __shfl_xor_sync(0xffffffffu, dot, o);
        }
        if (lane == 0) {
            const float inv = rsqrtf(fmaxf(ss, 1e-12f));
            const float avg = dot * inv * invc9;
            const float lam = lambda_so[r * PO + cb];
            out[b * PR + r] = fmaxf(lam * invc1, 0.0f) * (1.0f - avg);
        }
    }

    // ---- reset scratch for the next (graph-replayed) run ----
    __syncthreads();
    if (threadIdx.x < PD) g_s[b][threadIdx.x] = 0.0f;
    if (threadIdx.x == 0) { g_cnt[b] = 0.0f; g_ticket[b] = 0u; }
}

// ---------------------------------------------------------------------------
// Launch. Input order: l_local, h_context, lambda_so, center_o, o_types,
//                      adj_mask, two_hop_mask
// ---------------------------------------------------------------------------
extern "C" void kernel_launch(void* const* d_in, const int* in_sizes, int n_in,
                              void* d_out, int out_size) {
    const float* l_local   = (const float*)d_in[0];
    const float* h_context = (const float*)d_in[1];
    const float* lambda_so = (const float*)d_in[2];
    const int*   center_o  = (const int*)d_in[3];
    const int*   o_types   = (const int*)d_in[4];
    const int*   adj_mask  = (const int*)d_in[5];
    const int*   two_hop   = (const int*)d_in[6];
    float*       out       = (float*)d_out;

    dim3 grid(BLOCKS_PER_B, PB);
    ssfw_fused_kernel<<<grid, THREADS>>>(l_local, h_context, lambda_so,
                                         center_o, o_types, adj_mask, two_hop,
                                         out);
}

// round 11
// speedup vs baseline: 1.2145x; 1.0363x over previous
#include <cuda_runtime.h>
#include <cstdint>

// Problem constants: B=64, R=32, N=16384, D=64, O=8
#define PB 64
#define PR 32
#define PN 16384
#define PD 64
#define PO 8

#define BLOCKS_PER_B 16
#define THREADS 256          // 8 warps
#define WARPS (THREADS / 32)

// Global scratch (zero-initialized at load; the finalizing block resets it
// each run -> graph-replay-deterministic).
__device__ float        g_s[PB][PD];
__device__ float        g_cnt[PB];
__device__ unsigned int g_ticket[PB];

// acq_rel fetch-add on the ticket (replaces two __threadfence calls).
__device__ __forceinline__ unsigned int ticket_acq_rel(unsigned int* p) {
    unsigned int old;
    asm volatile("atom.acq_rel.gpu.global.add.u32 %0, [%1], 1;"
                 : "=r"(old) : "l"(p) : "memory");
    return old;
}

// fire-and-forget vector reduction: g_s push in 16 ops instead of 64
__device__ __forceinline__ void red_add_v4(float* p, float4 v) {
    asm volatile("red.global.add.v4.f32 [%0], {%1, %2, %3, %4};"
                 :: "l"(p), "f"(v.x), "f"(v.y), "f"(v.z), "f"(v.w)
                 : "memory");
}

// ---------------------------------------------------------------------------
// Grid (BLOCKS_PER_B, PB), 256 threads. Per warp: 128 rows = one int4 triplet
// per lane, all three LDG.128 front-batched (no other load traffic in phase 1
// -> 12.6 MB total, the irreducible floor).
// Gather: two valid rows in flight per iteration via 16-lane half-warps
// (lane16 -> float4 slice of the 256B row, 4-step shfl reduce).
// Block partial pushed to g_s with red.v4; last block per b (acq_rel ticket)
// loads l_local (only block that needs it), finalizes 32 outputs, resets
// scratch.
// ---------------------------------------------------------------------------
__global__ __launch_bounds__(THREADS)
void ssfw_fused_kernel(const float* __restrict__ l_local,
                       const float* __restrict__ h_context,
                       const float* __restrict__ lambda_so,
                       const int* __restrict__ center_o,
                       const int* __restrict__ o_types,
                       const int* __restrict__ adj_mask,
                       const int* __restrict__ two_hop_mask,
                       float* __restrict__ out) {
    __shared__ float s[PD];
    __shared__ float scnt;
    __shared__ int   sIsLast;

    const int b      = blockIdx.y;
    const int lane   = threadIdx.x & 31;
    const int warp   = threadIdx.x >> 5;
    const int half   = lane >> 4;        // 0 or 1
    const int lane16 = lane & 15;

    if (threadIdx.x < PD) s[threadIdx.x] = 0.0f;
    if (threadIdx.x == 0) scnt = 0.0f;

    // ---- front-batched independent loads (masks only) ----
    const int rowsPerBlock = PN / BLOCKS_PER_B;            // 1024
    const int rowsPerWarp  = rowsPerBlock / WARPS;         // 128
    const int base         = blockIdx.x * rowsPerBlock + warp * rowsPerWarp;
    const int vec          = (base >> 2) + lane;           // int4 index

    const int4* ot4 = (const int4*)(o_types      + (size_t)b * PN);
    const int4* am4 = (const int4*)(adj_mask     + (size_t)b * PN);
    const int4* th4 = (const int4*)(two_hop_mask + (size_t)b * PN);

    const int4 ot = __ldg(&ot4[vec]);
    const int4 am = __ldg(&am4[vec]);
    const int4 th = __ldg(&th4[vec]);

    const int cb = center_o[b];

    const bool v0 = ((am.x | th.x) != 0) && (ot.x == cb);
    const bool v1 = ((am.y | th.y) != 0) && (ot.y == cb);
    const bool v2 = ((am.z | th.z) != 0) && (ot.z == cb);
    const bool v3 = ((am.w | th.w) != 0) && (ot.w == cb);

    float ax = 0.0f, ay = 0.0f, az = 0.0f, aw = 0.0f;  // float4 slice acc
    int   cntw = 0;

    __syncthreads();   // smem zero-init visible

    const float* ctxBase = h_context + (size_t)b * PN * PD;

    // ---- gather: two valid rows in flight per iteration ----
    #pragma unroll
    for (int t = 0; t < 4; ++t) {
        const bool vt = (t == 0) ? v0 : (t == 1) ? v1 : (t == 2) ? v2 : v3;
        unsigned m = __ballot_sync(0xffffffffu, vt);
        cntw += __popc(m);
        while (m) {
            const int j0 = __ffs(m) - 1;
            m &= (m - 1);
            int j1 = -1;
            if (m) { j1 = __ffs(m) - 1; m &= (m - 1); }

            const int row0  = base + 4 * j0 + t;
            const int row1  = (j1 >= 0) ? (base + 4 * j1 + t) : row0;
            const int myrow = half ? row1 : row0;

            // 16 lanes x float4 = 256B row
            const float4 v =
                ((const float4*)(ctxBase + (size_t)myrow * PD))[lane16];
            float ss = v.x * v.x + v.y * v.y + v.z * v.z + v.w * v.w;
            #pragma unroll
            for (int o = 8; o; o >>= 1)      // stays within the 16-lane half
                ss += __shfl_xor_sync(0xffffffffu, ss, o);
            const float inv = rsqrtf(fmaxf(ss, 1e-12f));

            if (half == 0 || j1 >= 0) {      // half 1 idle when row1 absent
                ax += v.x * inv;
                ay += v.y * inv;
                az += v.z * inv;
                aw += v.w * inv;
            }
        }
    }

    // block-local reduction into smem (skip all-zero contributions)
    if (ax != 0.0f || ay != 0.0f || az != 0.0f || aw != 0.0f) {
        atomicAdd(&s[4 * lane16 + 0], ax);
        atomicAdd(&s[4 * lane16 + 1], ay);
        atomicAdd(&s[4 * lane16 + 2], az);
        atomicAdd(&s[4 * lane16 + 3], aw);
    }
    if (lane == 0 && cntw) atomicAdd(&scnt, (float)cntw);
    __syncthreads();

    // warp 0 pushes the block partial (16 red.v4); thread 0 bumps the ticket.
    if (warp == 0) {
        if (lane < 16) {
            const float4 sv = ((const float4*)s)[lane];
            red_add_v4(&g_s[b][4 * lane], sv);
        }
        if (lane == 0) {
            atomicAdd(&g_cnt[b], scnt);
            const unsigned old = ticket_acq_rel(&g_ticket[b]);
            sIsLast = (old == BLOCKS_PER_B - 1);
        }
    }
    __syncthreads();
    if (!sIsLast) return;

    // ---- Phase 2 (last block per b): finalize 32 outputs ----
    const float cntf  = g_cnt[b];
    const float invc9 = 1.0f / fmaxf(cntf, 1e-9f);
    const float invc1 = 1.0f / fmaxf(cntf, 1.0f);

    const float sx = g_s[b][2 * lane];
    const float sy = g_s[b][2 * lane + 1];

    #pragma unroll
    for (int rr = 0; rr < PR / WARPS; ++rr) {          // 4 rows per warp
        const int r = warp + rr * WARPS;
        const float2 v =
            ((const float2*)(l_local + ((size_t)b * PR + r) * PD))[lane];
        float ss  = v.x * v.x + v.y * v.y;
        float dot = v.x * sx + v.y * sy;
        #pragma unroll
        for (int o = 16; o; o >>= 1) {
            ss  += __shfl_xor_sync(0xffffffffu, ss,  o);
            dot += __shfl_xor_sync(0xffffffffu, dot, o);
        }
        if (lane == 0) {
            const float inv = rsqrtf(fmaxf(ss, 1e-12f));
            const float avg = dot * inv * invc9;
            const float lam = lambda_so[r * PO + cb];
            out[b * PR + r] = fmaxf(lam * invc1, 0.0f) * (1.0f - avg);
        }
    }

    // ---- reset scratch for the next (graph-replayed) run ----
    __syncthreads();
    if (threadIdx.x < PD) g_s[b][threadIdx.x] = 0.0f;
    if (threadIdx.x == 0) { g_cnt[b] = 0.0f; g_ticket[b] = 0u; }
}

// ---------------------------------------------------------------------------
// Launch. Input order: l_local, h_context, lambda_so, center_o, o_types,
//                      adj_mask, two_hop_mask
// ---------------------------------------------------------------------------
extern "C" void kernel_launch(void* const* d_in, const int* in_sizes, int n_in,
                              void* d_out, int out_size) {
    const float* l_local   = (const float*)d_in[0];
    const float* h_context = (const float*)d_in[1];
    const float* lambda_so = (const float*)d_in[2];
    const int*   center_o  = (const int*)d_in[3];
    const int*   o_types   = (const int*)d_in[4];
    const int*   adj_mask  = (const int*)d_in[5];
    const int*   two_hop   = (const int*)d_in[6];
    float*       out       = (float*)d_out;

    dim3 grid(BLOCKS_PER_B, PB);
    ssfw_fused_kernel<<<grid, THREADS>>>(l_local, h_context, lambda_so,
                                         center_o, o_types, adj_mask, two_hop,
                                         out);
}